// round 14
// baseline (speedup 1.0000x reference)
#include <cuda_runtime.h>
#include <cuda_bf16.h>

#define NB   8
#define NL   64
#define NH   8
#define ND   32
#define NHID 256

typedef unsigned long long u64;

// ---------------- static scratch (no runtime allocation) ----------------
__device__ __align__(16) float  g_WqkvT[NHID * 3 * NHID];  // [c][m*256+o]
__device__ __align__(16) float2 g_Ws2[NHID * 32];          // [c][e] = (wsq, wsv)
__device__ __align__(16) float g_q  [NB * NH * NL * ND];   // [b][h][l][d]
__device__ __align__(16) float g_k  [NB * NH * NL * ND];
__device__ __align__(16) float g_v  [NB * NH * NL * ND];
__device__ __align__(16) float g_kw [NB * NH * NL * ND];   // Wtk^T k
__device__ __align__(16) float g_qwl[NB * NH * NL * ND];   // Wtq^T q
__device__ float g_bk [NB * NH * NL];                      // btk . k
__device__ float g_bdq[NB * NH * NL];                      // btq . q
__device__ __align__(16) float g_sq [NB * NL * NL * ND];   // [b][i][j][d]
__device__ __align__(16) float g_sv [NB * NL * NL * ND];
__device__ __align__(16) float g_sqw[NB * NL * NL * ND];   // Wtq^T sq
__device__ float g_bsqd[NB * NL * NL];                     // btq . sq
__device__ float g_Zp[NB * NL * 2 * NH * NL];              // [bx2][h*64+k]
__device__ __align__(16) float g_Cp[NB * NL * 2 * NH * NL * ND];

// ---------------- packed f32x2 helpers ----------------
__device__ __forceinline__ void fma2(u64& d, u64 a, u64 b)
{
    asm("fma.rn.f32x2 %0, %1, %2, %0;" : "+l"(d) : "l"(a), "l"(b));
}
__device__ __forceinline__ u64 add2(u64 a, u64 b)
{
    u64 r; asm("add.rn.f32x2 %0, %1, %2;" : "=l"(r) : "l"(a), "l"(b)); return r;
}

// ---------------- K0: transpose / repack weights ----------------
__global__ void k_prep(const float* __restrict__ Wq, const float* __restrict__ Wk,
                       const float* __restrict__ Wv, const float* __restrict__ Wsq,
                       const float* __restrict__ Wsv)
{
    int c = blockIdx.x;                  // 0..255
    int t = threadIdx.x;                 // 0..767
    int m = t >> 8, o = t & 255;
    const float* W = (m == 0) ? Wq : (m == 1) ? Wk : Wv;
    g_WqkvT[c * 768 + t] = W[o * NHID + c];
    if (t < 32)
        g_Ws2[c * 32 + t] = make_float2(Wsq[t * NHID + c], Wsv[t * NHID + c]);
}

// ---------------- K1: q,k,v projections (4 rows / block) ----------------
__global__ __launch_bounds__(256)
void k_qkv(const float* __restrict__ hs, const float* __restrict__ bq,
           const float* __restrict__ bk, const float* __restrict__ bv)
{
    __shared__ __align__(16) float rows[4 * NHID];
    int r0 = blockIdx.x * 4;             // 128 blocks * 4 = 512 rows (b*64+l)
    int t = threadIdx.x;                 // output channel o
    float4* r4 = reinterpret_cast<float4*>(rows);
    const float4* h4 = reinterpret_cast<const float4*>(hs);
    r4[t] = h4[r0 * 64 + t];
    __syncthreads();

    float aq[4] = {0,0,0,0}, ak[4] = {0,0,0,0}, av[4] = {0,0,0,0};
    #pragma unroll 2
    for (int c4 = 0; c4 < 64; ++c4) {
        float wq[4], wk[4], wv[4];
        #pragma unroll
        for (int u = 0; u < 4; ++u) {
            int c = c4 * 4 + u;
            wq[u] = g_WqkvT[c * 768 + t];
            wk[u] = g_WqkvT[c * 768 + 256 + t];
            wv[u] = g_WqkvT[c * 768 + 512 + t];
        }
        #pragma unroll
        for (int rr = 0; rr < 4; ++rr) {
            float4 hv = reinterpret_cast<const float4*>(rows)[rr * 64 + c4];
            aq[rr] = fmaf(hv.x, wq[0], aq[rr]); aq[rr] = fmaf(hv.y, wq[1], aq[rr]);
            aq[rr] = fmaf(hv.z, wq[2], aq[rr]); aq[rr] = fmaf(hv.w, wq[3], aq[rr]);
            ak[rr] = fmaf(hv.x, wk[0], ak[rr]); ak[rr] = fmaf(hv.y, wk[1], ak[rr]);
            ak[rr] = fmaf(hv.z, wk[2], ak[rr]); ak[rr] = fmaf(hv.w, wk[3], ak[rr]);
            av[rr] = fmaf(hv.x, wv[0], av[rr]); av[rr] = fmaf(hv.y, wv[1], av[rr]);
            av[rr] = fmaf(hv.z, wv[2], av[rr]); av[rr] = fmaf(hv.w, wv[3], av[rr]);
        }
    }
    int hh = t >> 5, d = t & 31;
    #pragma unroll
    for (int rr = 0; rr < 4; ++rr) {
        int r = r0 + rr; int b = r >> 6, l = r & 63;
        int idx = ((b * NH + hh) * NL + l) * ND + d;
        g_q[idx] = aq[rr] + bq[t];
        g_k[idx] = ak[rr] + bk[t];
        g_v[idx] = av[rr] + bv[t];
    }
}

// ---------------- K1b: per-(b,h,l) transforms: qwl, kw, bdq, bk ----------
__global__ __launch_bounds__(256)
void k_small(const float* __restrict__ Wtq, const float* __restrict__ btq,
             const float* __restrict__ Wtk, const float* __restrict__ btk)
{
    int w = threadIdx.x >> 5, e = threadIdx.x & 31;
    int idx = blockIdx.x * 8 + w;        // 512*8 = 4096 = B*H*L rows
    float qv = g_q[idx * ND + e];
    float kv = g_k[idx * ND + e];
    float aq = 0.f, ak = 0.f;
    #pragma unroll
    for (int d = 0; d < ND; ++d) {
        float qd = __shfl_sync(0xffffffffu, qv, d);
        float kd = __shfl_sync(0xffffffffu, kv, d);
        aq = fmaf(Wtq[d * ND + e], qd, aq);
        ak = fmaf(Wtk[d * ND + e], kd, ak);
    }
    g_qwl[idx * ND + e] = aq;
    g_kw [idx * ND + e] = ak;
    float rq = btq[e] * qv, rk = btk[e] * kv;
    #pragma unroll
    for (int off = 16; off; off >>= 1) {
        rq += __shfl_xor_sync(0xffffffffu, rq, off);
        rk += __shfl_xor_sync(0xffffffffu, rk, off);
    }
    if (e == 0) { g_bdq[idx] = rq; g_bk[idx] = rk; }
}

// ---------------- K2: sq, sv = structure @ Ws{q,v}^T + b ----------------
// 1024 blocks, 32 rows/block; thread = (e, rowgroup): 4 rows x (sq,sv).
__global__ __launch_bounds__(256)
void k_sqsv(const float* __restrict__ structure, const float* __restrict__ bsq,
            const float* __restrict__ bsv)
{
    __shared__ __align__(16) float rows[32 * NHID];   // 32 KB
    int bx = blockIdx.x;                 // (b*64+i)*2 + jc
    int bi = bx >> 1, jc = bx & 1;
    int t = threadIdx.x;
    float4* r4 = reinterpret_cast<float4*>(rows);
    const float4* s4 = reinterpret_cast<const float4*>(structure);
    int base4 = (bi * 64 + jc * 32) * 64;
    #pragma unroll
    for (int u = 0; u < 8; ++u) r4[t + u * 256] = s4[base4 + t + u * 256];
    __syncthreads();

    int e = t & 31, rg = t >> 5;         // rg in [0,8): rows rg*4 .. rg*4+3
    float aq[4] = {0,0,0,0}, av[4] = {0,0,0,0};
    #pragma unroll 2
    for (int c4 = 0; c4 < 64; ++c4) {
        float2 w0 = g_Ws2[(c4 * 4 + 0) * 32 + e];
        float2 w1 = g_Ws2[(c4 * 4 + 1) * 32 + e];
        float2 w2 = g_Ws2[(c4 * 4 + 2) * 32 + e];
        float2 w3 = g_Ws2[(c4 * 4 + 3) * 32 + e];
        #pragma unroll
        for (int q = 0; q < 4; ++q) {
            float4 v = r4[(rg * 4 + q) * 64 + c4];
            aq[q] = fmaf(v.x, w0.x, aq[q]); aq[q] = fmaf(v.y, w1.x, aq[q]);
            aq[q] = fmaf(v.z, w2.x, aq[q]); aq[q] = fmaf(v.w, w3.x, aq[q]);
            av[q] = fmaf(v.x, w0.y, av[q]); av[q] = fmaf(v.y, w1.y, av[q]);
            av[q] = fmaf(v.z, w2.y, av[q]); av[q] = fmaf(v.w, w3.y, av[q]);
        }
    }
    float bq_ = bsq[e], bv_ = bsv[e];
    #pragma unroll
    for (int q = 0; q < 4; ++q) {
        int j = jc * 32 + rg * 4 + q;
        g_sq[(bi * NL + j) * ND + e] = aq[q] + bq_;
        g_sv[(bi * NL + j) * ND + e] = av[q] + bv_;
    }
}

// ---------------- K3: sqw = Wtq^T sq, bsqd = btq . sq ----------------
__global__ __launch_bounds__(256)
void k_sqw(const float* __restrict__ Wtq, const float* __restrict__ btq)
{
    int w = threadIdx.x >> 5, e = threadIdx.x & 31;
    int row = blockIdx.x * 8 + w;        // 4096*8 = 32768 = B*L*L rows
    float sv = g_sq[row * ND + e];
    float acc = 0.f;
    #pragma unroll
    for (int d = 0; d < ND; ++d)
        acc = fmaf(Wtq[d * ND + e], __shfl_sync(0xffffffffu, sv, d), acc);
    g_sqw[row * ND + e] = acc;
    float r = btq[e] * sv;
    #pragma unroll
    for (int off = 16; off; off >>= 1) r += __shfl_xor_sync(0xffffffffu, r, off);
    if (e == 0) g_bsqd[row] = r;
}

// ---------------- cp.async helper ----------------
__device__ __forceinline__ void cp_async16(void* smem, const void* gmem)
{
    unsigned sa = (unsigned)__cvta_generic_to_shared(smem);
    asm volatile("cp.async.cg.shared.global [%0], [%1], 16;" :: "r"(sa), "l"(gmem));
}

// ---------------- MAIN: fused scores + online softmax + ctx partials ----
// grid = 1024 blocks: (b,i) x j-half; 512 threads = (h,k). Packed f32x2.
__global__ __launch_bounds__(512, 1)
void k_main(const float* __restrict__ triple, const float* __restrict__ mask)
{
    const int bx2  = blockIdx.x;
    const int pair = bx2 >> 1;           // b*64 + i
    const int half = bx2 & 1;
    const int b  = pair >> 6, i = pair & 63;
    const int j0 = half * 32;
    const int t  = threadIdx.x;
    const int h  = t >> 6, k = t & 63;

    __shared__ __align__(16) float4 trip_s[3][576];   // [k][d4] row-stride 9
    __shared__ __align__(16) float  q5_s[2][256];     // [h][d]
    __shared__ __align__(16) float  v5_s[2][256];
    __shared__ __align__(16) float  qw_s[2][256];
    __shared__ float bq5_s[2][8];
    __shared__ float mask_s[64];

    const float4* tg4 = reinterpret_cast<const float4*>(triple);
    const int h2 = t >> 5, d2 = t & 31;               // staging roles (t<256)

    float qi_r = 0.f, vi_r = 0.f, qwl_i_r = 0.f, bdq_i_r = 0.f;
    if (t < 256) {
        qi_r    = g_q  [((b * NH + h2) * NL + i) * ND + d2];
        vi_r    = g_v  [((b * NH + h2) * NL + i) * ND + d2];
        qwl_i_r = g_qwl[((b * NH + h2) * NL + i) * ND + d2];
    }
    if (t < 8) bdq_i_r = g_bdq[(b * NH + t) * NL + i];
    if (t < 64) mask_s[t] = mask[b * NL + t];

    // per-thread constants: k row and kw row as packed f32x2 pairs
    u64 kvec2[16], kw2[16];
    {
        const ulonglong2* ka = reinterpret_cast<const ulonglong2*>(g_k  + ((b * NH + h) * NL + k) * ND);
        const ulonglong2* kb = reinterpret_cast<const ulonglong2*>(g_kw + ((b * NH + h) * NL + k) * ND);
        #pragma unroll
        for (int d4 = 0; d4 < 8; ++d4) {
            ulonglong2 x = ka[d4];
            kvec2[2*d4] = x.x; kvec2[2*d4+1] = x.y;
            ulonglong2 y = kb[d4];
            kw2[2*d4] = y.x; kw2[2*d4+1] = y.y;
        }
    }
    const float bkdot = g_bk[(b * NH + h) * NL + k];
    const float mik = mask[b * NL + i] * mask[b * NL + k];

    // ---- prologue: stage triple rows j0, j0+1; smalls for j0 ----
    cp_async16(&trip_s[0][(t >> 3) * 9 + (t & 7)], &tg4[(pair * 64 + j0) * 512 + t]);
    asm volatile("cp.async.commit_group;");
    cp_async16(&trip_s[1][(t >> 3) * 9 + (t & 7)], &tg4[(pair * 64 + j0 + 1) * 512 + t]);
    asm volatile("cp.async.commit_group;");
    if (t < 256) {
        int p = pair * 64 + j0;
        q5_s[0][t] = qi_r + g_q[((b * NH + h2) * NL + j0) * ND + d2] + g_sq[p * ND + d2];
        v5_s[0][t] = vi_r + g_v[((b * NH + h2) * NL + j0) * ND + d2] + g_sv[p * ND + d2];
        qw_s[0][t] = qwl_i_r + g_qwl[((b * NH + h2) * NL + j0) * ND + d2] + g_sqw[p * ND + d2];
    }
    if (t < 8)
        bq5_s[0][t] = bdq_i_r + g_bdq[(b * NH + t) * NL + j0] + g_bsqd[pair * 64 + j0];
    asm volatile("cp.async.wait_group 1;");
    __syncthreads();

    u64 C2[16];
    #pragma unroll
    for (int d = 0; d < 16; ++d) C2[d] = 0ull;
    float Z = 0.f;

    for (int jj = 0; jj < 32; ++jj) {
        const int j = j0 + jj;
        const int cur = jj & 1, nxt = cur ^ 1;

        // prefetch triple row j+2 (distance 2, 3 buffers)
        if (jj < 30)
            cp_async16(&trip_s[(jj + 2) % 3][(t >> 3) * 9 + (t & 7)],
                       &tg4[(pair * 64 + j + 2) * 512 + t]);
        asm volatile("cp.async.commit_group;");

        // load smalls for j+1 into regs
        const int jn = (jj < 31) ? j + 1 : j;
        float q5n = 0.f, v5n = 0.f, qwn = 0.f, bn = 0.f;
        if (t < 256) {
            int p = pair * 64 + jn;
            q5n = qi_r + g_q[((b * NH + h2) * NL + jn) * ND + d2] + g_sq[p * ND + d2];
            v5n = vi_r + g_v[((b * NH + h2) * NL + jn) * ND + d2] + g_sv[p * ND + d2];
            qwn = qwl_i_r + g_qwl[((b * NH + h2) * NL + jn) * ND + d2] + g_sqw[p * ND + d2];
        }
        if (t < 8)
            bn = bdq_i_r + g_bdq[(b * NH + t) * NL + jn] + g_bsqd[pair * 64 + jn];

        // score: s = q5.k + trip.(qw + kw) + bq5 + bk   (packed f32x2)
        u64 s2a = 0ull, s2b = 0ull;
        const ulonglong2* tb  = reinterpret_cast<const ulonglong2*>(&trip_s[jj % 3][k * 9]);
        const ulonglong2* q54 = reinterpret_cast<const ulonglong2*>(&q5_s[cur][h * ND]);
        const ulonglong2* qw4 = reinterpret_cast<const ulonglong2*>(&qw_s[cur][h * ND]);
        #pragma unroll
        for (int d4 = 0; d4 < 8; ++d4) {
            ulonglong2 tp = tb[d4];
            ulonglong2 qa = q54[d4];
            ulonglong2 qq = qw4[d4];
            fma2(s2a, kvec2[2*d4],     qa.x);
            fma2(s2a, kvec2[2*d4 + 1], qa.y);
            fma2(s2b, tp.x, add2(qq.x, kw2[2*d4]));
            fma2(s2b, tp.y, add2(qq.y, kw2[2*d4 + 1]));
        }
        u64 st = add2(s2a, s2b);
        unsigned lo_u, hi_u;
        asm("mov.b64 {%0, %1}, %2;" : "=r"(lo_u), "=r"(hi_u) : "l"(st));
        float s = __uint_as_float(lo_u) + __uint_as_float(hi_u) + bq5_s[cur][h] + bkdot;
        s = fmaf(s, 0.17677669529663687f, mik * mask_s[j]);   // /sqrt(32) + mask3
        float w = __expf(s);
        Z += w;
        u64 w2;
        {
            unsigned wu = __float_as_uint(w);
            asm("mov.b64 %0, {%1, %2};" : "=l"(w2) : "r"(wu), "r"(wu));
        }
        const ulonglong2* v54 = reinterpret_cast<const ulonglong2*>(&v5_s[cur][h * ND]);
        #pragma unroll
        for (int d4 = 0; d4 < 8; ++d4) {
            ulonglong2 vv = v54[d4];
            fma2(C2[2*d4],     w2, vv.x);
            fma2(C2[2*d4 + 1], w2, vv.y);
        }

        // stash smalls for j+1
        if (t < 256) { q5_s[nxt][t] = q5n; v5_s[nxt][t] = v5n; qw_s[nxt][t] = qwn; }
        if (t < 8) bq5_s[nxt][t] = bn;
        asm volatile("cp.async.wait_group 1;");
        __syncthreads();
    }

    // write partials
    g_Zp[bx2 * 512 + t] = Z;
    ulonglong2* cp = reinterpret_cast<ulonglong2*>(g_Cp + (bx2 * 512 + t) * ND);
    #pragma unroll
    for (int d4 = 0; d4 < 8; ++d4) {
        ulonglong2 o; o.x = C2[2*d4]; o.y = C2[2*d4 + 1];
        cp[d4] = o;
    }
}

// ---------------- Reduce partials over (i, half); out [b][k][h*32+d] ----
__global__ __launch_bounds__(256)
void k_reduce(float* __restrict__ out)
{
    const int blk = blockIdx.x;          // b*64 + kk (512 blocks)
    const int b = blk >> 6, kk = blk & 63;
    const int t = threadIdx.x;           // h*32 + d
    const int h = t >> 5, d = t & 31;
    float sz = 0.f, sc = 0.f;
    #pragma unroll 4
    for (int u = 0; u < 128; ++u) {      // u = i*2 + half
        int bi = (b * 64) * 2 + u;
        int zi = bi * 512 + h * 64 + kk;
        sz += g_Zp[zi];
        sc += g_Cp[zi * ND + d];
    }
    out[blk * 256 + t] = sc / sz;
}

// ---------------- launch ----------------
extern "C" void kernel_launch(void* const* d_in, const int* in_sizes, int n_in,
                              void* d_out, int out_size)
{
    const float* hs        = (const float*)d_in[0];
    const float* mask      = (const float*)d_in[1];
    const float* structure = (const float*)d_in[2];
    const float* triple    = (const float*)d_in[3];
    const float* Wq  = (const float*)d_in[4];
    const float* bq  = (const float*)d_in[5];
    const float* Wk  = (const float*)d_in[6];
    const float* bk  = (const float*)d_in[7];
    const float* Wv  = (const float*)d_in[8];
    const float* bv  = (const float*)d_in[9];
    const float* Wsq = (const float*)d_in[10];
    const float* bsq = (const float*)d_in[11];
    const float* Wsv = (const float*)d_in[12];
    const float* bsv = (const float*)d_in[13];
    const float* Wtq = (const float*)d_in[14];
    const float* btq = (const float*)d_in[15];
    const float* Wtk = (const float*)d_in[16];
    const float* btk = (const float*)d_in[17];
    float* out = (float*)d_out;

    k_prep <<<256, 768>>>(Wq, Wk, Wv, Wsq, Wsv);
    k_qkv  <<<128, 256>>>(hs, bq, bk, bv);
    k_small<<<512, 256>>>(Wtq, btq, Wtk, btk);
    k_sqsv <<<1024, 256>>>(structure, bsq, bsv);
    k_sqw  <<<4096, 256>>>(Wtq, btq);
    k_main <<<1024, 512>>>(triple, mask);
    k_reduce<<<512, 256>>>(out);
}

// round 15
// speedup vs baseline: 1.2820x; 1.2820x over previous
#include <cuda_runtime.h>
#include <cuda_bf16.h>

#define NB   8
#define NL   64
#define NH   8
#define ND   32
#define NHID 256

typedef unsigned long long u64;

// ---------------- static scratch (no runtime allocation) ----------------
__device__ __align__(16) float  g_WqkvT[NHID * 3 * NHID];  // [c][m*256+o]
__device__ __align__(16) float2 g_Ws2[NHID * 32];          // [c][e] = (wsq, wsv)
__device__ __align__(16) float g_q  [NB * NH * NL * ND];   // [b][h][l][d]
__device__ __align__(16) float g_k  [NB * NH * NL * ND];
__device__ __align__(16) float g_v  [NB * NH * NL * ND];
__device__ __align__(16) float g_kw [NB * NH * NL * ND];   // Wtk^T k
__device__ __align__(16) float g_qwl[NB * NH * NL * ND];   // Wtq^T q
__device__ float g_bk [NB * NH * NL];                      // btk . k
__device__ float g_bdq[NB * NH * NL];                      // btq . q
__device__ __align__(16) float g_sq [NB * NL * NL * ND];   // [b][i][j][d]
__device__ __align__(16) float g_sv [NB * NL * NL * ND];
__device__ __align__(16) float g_sqw[NB * NL * NL * ND];   // Wtq^T sq
__device__ float g_bsqd[NB * NL * NL];                     // btq . sq
__device__ float g_Zp[NB * NL * 2 * NH * NL];              // [bx2][h*64+k]
__device__ __align__(16) float g_Cp[NB * NL * 2 * NH * NL * ND];

// ---------------- packed f32x2 helpers ----------------
__device__ __forceinline__ void fma2(u64& d, u64 a, u64 b)
{
    asm("fma.rn.f32x2 %0, %1, %2, %0;" : "+l"(d) : "l"(a), "l"(b));
}
__device__ __forceinline__ u64 add2(u64 a, u64 b)
{
    u64 r; asm("add.rn.f32x2 %0, %1, %2;" : "=l"(r) : "l"(a), "l"(b)); return r;
}

// ---------------- K0: transpose / repack weights ----------------
__global__ void k_prep(const float* __restrict__ Wq, const float* __restrict__ Wk,
                       const float* __restrict__ Wv, const float* __restrict__ Wsq,
                       const float* __restrict__ Wsv)
{
    int c = blockIdx.x;                  // 0..255
    int t = threadIdx.x;                 // 0..767
    int m = t >> 8, o = t & 255;
    const float* W = (m == 0) ? Wq : (m == 1) ? Wk : Wv;
    g_WqkvT[c * 768 + t] = W[o * NHID + c];
    if (t < 32)
        g_Ws2[c * 32 + t] = make_float2(Wsq[t * NHID + c], Wsv[t * NHID + c]);
}

// ---------------- K1: q,k,v projections (4 rows / block) ----------------
__global__ __launch_bounds__(256)
void k_qkv(const float* __restrict__ hs, const float* __restrict__ bq,
           const float* __restrict__ bk, const float* __restrict__ bv)
{
    __shared__ __align__(16) float rows[4 * NHID];
    int r0 = blockIdx.x * 4;             // 128 blocks * 4 = 512 rows (b*64+l)
    int t = threadIdx.x;                 // output channel o
    float4* r4 = reinterpret_cast<float4*>(rows);
    const float4* h4 = reinterpret_cast<const float4*>(hs);
    r4[t] = h4[r0 * 64 + t];
    __syncthreads();

    float aq[4] = {0,0,0,0}, ak[4] = {0,0,0,0}, av[4] = {0,0,0,0};
    #pragma unroll 2
    for (int c4 = 0; c4 < 64; ++c4) {
        float wq[4], wk[4], wv[4];
        #pragma unroll
        for (int u = 0; u < 4; ++u) {
            int c = c4 * 4 + u;
            wq[u] = g_WqkvT[c * 768 + t];
            wk[u] = g_WqkvT[c * 768 + 256 + t];
            wv[u] = g_WqkvT[c * 768 + 512 + t];
        }
        #pragma unroll
        for (int rr = 0; rr < 4; ++rr) {
            float4 hv = reinterpret_cast<const float4*>(rows)[rr * 64 + c4];
            aq[rr] = fmaf(hv.x, wq[0], aq[rr]); aq[rr] = fmaf(hv.y, wq[1], aq[rr]);
            aq[rr] = fmaf(hv.z, wq[2], aq[rr]); aq[rr] = fmaf(hv.w, wq[3], aq[rr]);
            ak[rr] = fmaf(hv.x, wk[0], ak[rr]); ak[rr] = fmaf(hv.y, wk[1], ak[rr]);
            ak[rr] = fmaf(hv.z, wk[2], ak[rr]); ak[rr] = fmaf(hv.w, wk[3], ak[rr]);
            av[rr] = fmaf(hv.x, wv[0], av[rr]); av[rr] = fmaf(hv.y, wv[1], av[rr]);
            av[rr] = fmaf(hv.z, wv[2], av[rr]); av[rr] = fmaf(hv.w, wv[3], av[rr]);
        }
    }
    int hh = t >> 5, d = t & 31;
    #pragma unroll
    for (int rr = 0; rr < 4; ++rr) {
        int r = r0 + rr; int b = r >> 6, l = r & 63;
        int idx = ((b * NH + hh) * NL + l) * ND + d;
        g_q[idx] = aq[rr] + bq[t];
        g_k[idx] = ak[rr] + bk[t];
        g_v[idx] = av[rr] + bv[t];
    }
}

// ---------------- K1b: per-(b,h,l) transforms: qwl, kw, bdq, bk ----------
__global__ __launch_bounds__(256)
void k_small(const float* __restrict__ Wtq, const float* __restrict__ btq,
             const float* __restrict__ Wtk, const float* __restrict__ btk)
{
    int w = threadIdx.x >> 5, e = threadIdx.x & 31;
    int idx = blockIdx.x * 8 + w;        // 512*8 = 4096 = B*H*L rows
    float qv = g_q[idx * ND + e];
    float kv = g_k[idx * ND + e];
    float aq = 0.f, ak = 0.f;
    #pragma unroll
    for (int d = 0; d < ND; ++d) {
        float qd = __shfl_sync(0xffffffffu, qv, d);
        float kd = __shfl_sync(0xffffffffu, kv, d);
        aq = fmaf(Wtq[d * ND + e], qd, aq);
        ak = fmaf(Wtk[d * ND + e], kd, ak);
    }
    g_qwl[idx * ND + e] = aq;
    g_kw [idx * ND + e] = ak;
    float rq = btq[e] * qv, rk = btk[e] * kv;
    #pragma unroll
    for (int off = 16; off; off >>= 1) {
        rq += __shfl_xor_sync(0xffffffffu, rq, off);
        rk += __shfl_xor_sync(0xffffffffu, rk, off);
    }
    if (e == 0) { g_bdq[idx] = rq; g_bk[idx] = rk; }
}

// ---------------- K2: sq, sv = structure @ Ws{q,v}^T + b ----------------
__global__ __launch_bounds__(256)
void k_sqsv(const float* __restrict__ structure, const float* __restrict__ bsq,
            const float* __restrict__ bsv)
{
    __shared__ __align__(16) float rows[32 * NHID];   // 32 KB
    int bx = blockIdx.x;                 // (b*64+i)*2 + jc
    int bi = bx >> 1, jc = bx & 1;
    int t = threadIdx.x;
    float4* r4 = reinterpret_cast<float4*>(rows);
    const float4* s4 = reinterpret_cast<const float4*>(structure);
    int base4 = (bi * 64 + jc * 32) * 64;
    #pragma unroll
    for (int u = 0; u < 8; ++u) r4[t + u * 256] = s4[base4 + t + u * 256];
    __syncthreads();

    int e = t & 31, rg = t >> 5;         // rg in [0,8): rows rg*4 .. rg*4+3
    float aq[4] = {0,0,0,0}, av[4] = {0,0,0,0};
    #pragma unroll 2
    for (int c4 = 0; c4 < 64; ++c4) {
        float2 w0 = g_Ws2[(c4 * 4 + 0) * 32 + e];
        float2 w1 = g_Ws2[(c4 * 4 + 1) * 32 + e];
        float2 w2 = g_Ws2[(c4 * 4 + 2) * 32 + e];
        float2 w3 = g_Ws2[(c4 * 4 + 3) * 32 + e];
        #pragma unroll
        for (int q = 0; q < 4; ++q) {
            float4 v = r4[(rg * 4 + q) * 64 + c4];
            aq[q] = fmaf(v.x, w0.x, aq[q]); aq[q] = fmaf(v.y, w1.x, aq[q]);
            aq[q] = fmaf(v.z, w2.x, aq[q]); aq[q] = fmaf(v.w, w3.x, aq[q]);
            av[q] = fmaf(v.x, w0.y, av[q]); av[q] = fmaf(v.y, w1.y, av[q]);
            av[q] = fmaf(v.z, w2.y, av[q]); av[q] = fmaf(v.w, w3.y, av[q]);
        }
    }
    float bq_ = bsq[e], bv_ = bsv[e];
    #pragma unroll
    for (int q = 0; q < 4; ++q) {
        int j = jc * 32 + rg * 4 + q;
        g_sq[(bi * NL + j) * ND + e] = aq[q] + bq_;
        g_sv[(bi * NL + j) * ND + e] = av[q] + bv_;
    }
}

// ---------------- K3: sqw = Wtq^T sq, bsqd = btq . sq ----------------
__global__ __launch_bounds__(256)
void k_sqw(const float* __restrict__ Wtq, const float* __restrict__ btq)
{
    int w = threadIdx.x >> 5, e = threadIdx.x & 31;
    int row = blockIdx.x * 8 + w;        // 4096*8 = 32768 = B*L*L rows
    float sv = g_sq[row * ND + e];
    float acc = 0.f;
    #pragma unroll
    for (int d = 0; d < ND; ++d)
        acc = fmaf(Wtq[d * ND + e], __shfl_sync(0xffffffffu, sv, d), acc);
    g_sqw[row * ND + e] = acc;
    float r = btq[e] * sv;
    #pragma unroll
    for (int off = 16; off; off >>= 1) r += __shfl_xor_sync(0xffffffffu, r, off);
    if (e == 0) g_bsqd[row] = r;
}

// ---------------- cp.async helper ----------------
__device__ __forceinline__ void cp_async16(void* smem, const void* gmem)
{
    unsigned sa = (unsigned)__cvta_generic_to_shared(smem);
    asm volatile("cp.async.cg.shared.global [%0], [%1], 16;" :: "r"(sa), "l"(gmem));
}

// ---------------- MAIN smem layout (dynamic, bytes) ----------------
#define OFF_TRIP 0                        // float4[2][4][576] = 73728
#define OFF_CQ   73728                    // float [2][1024]   = 8192
#define OFF_CV   81920
#define OFF_CQW  90112
#define OFF_SQX  98304                    // float [2][4][96]  = 3072
#define OFF_BQ5  101376                   // float [32][8]     = 1024
#define OFF_QI   102400                   // float [256]
#define OFF_VI   103424
#define OFF_QWI  104448
#define OFF_MASK 105472                   // float [64]
#define SMEM_MAIN 105728

// ---------------- MAIN: chunked (4 j / sync), all-cp.async staging -------
// grid = 1024 blocks: (b,i) x j-half; 512 threads = (h,k).
__global__ __launch_bounds__(512, 1)
void k_main(const float* __restrict__ triple, const float* __restrict__ mask)
{
    extern __shared__ __align__(16) char sm[];
    float4* trip  = reinterpret_cast<float4*>(sm + OFF_TRIP);  // [p*2304 + jj*576 + k*9 + d4]
    float*  cq    = reinterpret_cast<float*>(sm + OFF_CQ);     // [p*1024 + jj*256 + h*32 + d]
    float*  cv    = reinterpret_cast<float*>(sm + OFF_CV);
    float*  cqw   = reinterpret_cast<float*>(sm + OFF_CQW);
    float*  sqx   = reinterpret_cast<float*>(sm + OFF_SQX);    // [p*384 + jj*96 + a*32 + d]
    float*  bq5s  = reinterpret_cast<float*>(sm + OFF_BQ5);    // [jr*8 + h]
    float*  qi_s  = reinterpret_cast<float*>(sm + OFF_QI);
    float*  vi_s  = reinterpret_cast<float*>(sm + OFF_VI);
    float*  qwi_s = reinterpret_cast<float*>(sm + OFF_QWI);
    float*  mask_s= reinterpret_cast<float*>(sm + OFF_MASK);

    const int bx2  = blockIdx.x;
    const int pair = bx2 >> 1;           // b*64 + i
    const int half = bx2 & 1;
    const int b  = pair >> 6, i = pair & 63;
    const int j0 = half * 32;
    const int t  = threadIdx.x;
    const int h  = t >> 6, k = t & 63;

    const float4* tg4 = reinterpret_cast<const float4*>(triple);
    const float4* gq4 = reinterpret_cast<const float4*>(g_q);
    const float4* gv4 = reinterpret_cast<const float4*>(g_v);
    const float4* gw4 = reinterpret_cast<const float4*>(g_qwl);
    const float4* sq4 = reinterpret_cast<const float4*>(g_sq);
    const float4* sv4 = reinterpret_cast<const float4*>(g_sv);
    const float4* sw4 = reinterpret_cast<const float4*>(g_sqw);

    // ---- prologue: per-block constants into smem ----
    if (t < 256) {
        int h2 = t >> 5, d2 = t & 31;
        qi_s [t] = g_q  [((b * NH + h2) * NL + i) * ND + d2];
        vi_s [t] = g_v  [((b * NH + h2) * NL + i) * ND + d2];
        qwi_s[t] = g_qwl[((b * NH + h2) * NL + i) * ND + d2];
        // bq5 for all 32 j of this half: jr = t>>3, hh = t&7
        int jr = t >> 3, hh = t & 7;
        bq5s[t] = g_bdq[(b * NH + hh) * NL + i]
                + g_bdq[(b * NH + hh) * NL + (j0 + jr)]
                + g_bsqd[pair * NL + j0 + jr];
    }
    if (t < 64) mask_s[t] = mask[b * NL + t];

    // per-thread constants: k row and kw row as packed f32x2
    u64 kvec2[16], kw2[16];
    {
        const ulonglong2* ka = reinterpret_cast<const ulonglong2*>(g_k  + ((b * NH + h) * NL + k) * ND);
        const ulonglong2* kb = reinterpret_cast<const ulonglong2*>(g_kw + ((b * NH + h) * NL + k) * ND);
        #pragma unroll
        for (int d4 = 0; d4 < 8; ++d4) {
            ulonglong2 x = ka[d4];
            kvec2[2*d4] = x.x; kvec2[2*d4+1] = x.y;
            ulonglong2 y = kb[d4];
            kw2[2*d4] = y.x; kw2[2*d4+1] = y.y;
        }
    }
    const float bkdot = g_bk[(b * NH + h) * NL + k];
    const float mik = mask[b * NL + i] * mask[b * NL + k];

    // ---- staging lambda-ish macro: stage chunk (4 j) into buffer p ----
    #define STAGE_CHUNK(cidx, p)                                                     \
    {                                                                                \
        const int jb = j0 + (cidx) * 4;                                              \
        _Pragma("unroll")                                                            \
        for (int jj = 0; jj < 4; ++jj)                                               \
            cp_async16(&trip[(p) * 2304 + jj * 576 + (t >> 3) * 9 + (t & 7)],        \
                       &tg4[(pair * 64 + jb + jj) * 512 + t]);                       \
        {   /* raw rows: r = t (all 512) and r = t+512 (t<256): 768 float4 */        \
            int r = t;                                                               \
            int a = r >> 8, rem = r & 255;                                           \
            int jj = rem >> 6, hh = (rem >> 3) & 7, q = rem & 7;                     \
            const float4* src = (a == 0) ? gq4 : gv4;                                \
            float* dstb = (a == 0) ? cq : cv;                                        \
            cp_async16(&dstb[(p) * 1024 + jj * 256 + hh * 32 + q * 4],               \
                       &src[((b * NH + hh) * NL + jb + jj) * 8 + q]);                \
            if (t < 256) {                                                           \
                int rem2 = t; int jj2 = rem2 >> 6, hh2 = (rem2 >> 3) & 7, q2 = rem2 & 7; \
                cp_async16(&cqw[(p) * 1024 + jj2 * 256 + hh2 * 32 + q2 * 4],         \
                           &gw4[((b * NH + hh2) * NL + jb + jj2) * 8 + q2]);         \
            }                                                                        \
        }                                                                            \
        if (t < 96) {   /* sq/sv/sqw rows: 96 float4 */                              \
            int a2 = t >> 5, rem = t & 31;                                           \
            int jj = rem >> 3, q = rem & 7;                                          \
            const float4* src = (a2 == 0) ? sq4 : (a2 == 1) ? sv4 : sw4;             \
            cp_async16(&sqx[(p) * 384 + jj * 96 + a2 * 32 + q * 4],                  \
                       &src[(pair * 64 + jb + jj) * 8 + q]);                         \
        }                                                                            \
        asm volatile("cp.async.commit_group;");                                      \
    }

    STAGE_CHUNK(0, 0);

    u64 C2[16];
    #pragma unroll
    for (int d = 0; d < 16; ++d) C2[d] = 0ull;
    float Z = 0.f;

    for (int c = 0; c < 8; ++c) {
        const int p = c & 1;
        asm volatile("cp.async.wait_group 0;");
        __syncthreads();                              // chunk c data visible

        if (c < 7) STAGE_CHUNK(c + 1, p ^ 1);         // prefetch next chunk

        // fixup: combined = raw + (i-row) + (sq-ish row)
        {
            int r, jj, hd, d;
            r = t;        jj = r >> 8; hd = r & 255; d = hd & 31;
            cq [p*1024 + r] += qi_s [hd] + sqx[p*384 + jj*96 +      d];
            r = t + 512;  jj = r >> 8; hd = r & 255; d = hd & 31;
            cq [p*1024 + r] += qi_s [hd] + sqx[p*384 + jj*96 +      d];
            r = t;        jj = r >> 8; hd = r & 255; d = hd & 31;
            cv [p*1024 + r] += vi_s [hd] + sqx[p*384 + jj*96 + 32 + d];
            r = t + 512;  jj = r >> 8; hd = r & 255; d = hd & 31;
            cv [p*1024 + r] += vi_s [hd] + sqx[p*384 + jj*96 + 32 + d];
            r = t;        jj = r >> 8; hd = r & 255; d = hd & 31;
            cqw[p*1024 + r] += qwi_s[hd] + sqx[p*384 + jj*96 + 64 + d];
            r = t + 512;  jj = r >> 8; hd = r & 255; d = hd & 31;
            cqw[p*1024 + r] += qwi_s[hd] + sqx[p*384 + jj*96 + 64 + d];
        }
        __syncthreads();                              // fixup visible

        // ---- compute 4 j back-to-back, no syncs ----
        #pragma unroll
        for (int jj = 0; jj < 4; ++jj) {
            const int jr = c * 4 + jj;
            u64 s2a = 0ull, s2b = 0ull;
            const ulonglong2* tb  = reinterpret_cast<const ulonglong2*>(&trip[p*2304 + jj*576 + k*9]);
            const ulonglong2* qa4 = reinterpret_cast<const ulonglong2*>(&cq [p*1024 + jj*256 + h*32]);
            const ulonglong2* qw4 = reinterpret_cast<const ulonglong2*>(&cqw[p*1024 + jj*256 + h*32]);
            #pragma unroll
            for (int d4 = 0; d4 < 8; ++d4) {
                ulonglong2 tp = tb[d4];
                ulonglong2 qa = qa4[d4];
                ulonglong2 qq = qw4[d4];
                fma2(s2a, kvec2[2*d4],     qa.x);
                fma2(s2a, kvec2[2*d4 + 1], qa.y);
                fma2(s2b, tp.x, add2(qq.x, kw2[2*d4]));
                fma2(s2b, tp.y, add2(qq.y, kw2[2*d4 + 1]));
            }
            u64 st = add2(s2a, s2b);
            unsigned lo_u, hi_u;
            asm("mov.b64 {%0, %1}, %2;" : "=r"(lo_u), "=r"(hi_u) : "l"(st));
            float s = __uint_as_float(lo_u) + __uint_as_float(hi_u)
                    + bq5s[jr * 8 + h] + bkdot;
            s = fmaf(s, 0.17677669529663687f, mik * mask_s[j0 + jr]);
            float w = __expf(s);
            Z += w;
            u64 w2;
            {
                unsigned wu = __float_as_uint(w);
                asm("mov.b64 %0, {%1, %2};" : "=l"(w2) : "r"(wu), "r"(wu));
            }
            const ulonglong2* vv4 = reinterpret_cast<const ulonglong2*>(&cv[p*1024 + jj*256 + h*32]);
            #pragma unroll
            for (int d4 = 0; d4 < 8; ++d4) {
                ulonglong2 vv = vv4[d4];
                fma2(C2[2*d4],     w2, vv.x);
                fma2(C2[2*d4 + 1], w2, vv.y);
            }
        }
    }

    // write partials
    g_Zp[bx2 * 512 + t] = Z;
    ulonglong2* cpo = reinterpret_cast<ulonglong2*>(g_Cp + (bx2 * 512 + t) * ND);
    #pragma unroll
    for (int d4 = 0; d4 < 8; ++d4) {
        ulonglong2 o; o.x = C2[2*d4]; o.y = C2[2*d4 + 1];
        cpo[d4] = o;
    }
    #undef STAGE_CHUNK
}

// ---------------- Reduce partials over (i, half); out [b][k][h*32+d] ----
__global__ __launch_bounds__(256)
void k_reduce(float* __restrict__ out)
{
    const int blk = blockIdx.x;          // b*64 + kk (512 blocks)
    const int b = blk >> 6, kk = blk & 63;
    const int t = threadIdx.x;           // h*32 + d
    const int h = t >> 5, d = t & 31;
    float sz = 0.f, sc = 0.f;
    #pragma unroll 4
    for (int u = 0; u < 128; ++u) {      // u = i*2 + half
        int bi = (b * 64) * 2 + u;
        int zi = bi * 512 + h * 64 + kk;
        sz += g_Zp[zi];
        sc += g_Cp[zi * ND + d];
    }
    out[blk * 256 + t] = sc / sz;
}

// ---------------- launch ----------------
extern "C" void kernel_launch(void* const* d_in, const int* in_sizes, int n_in,
                              void* d_out, int out_size)
{
    const float* hs        = (const float*)d_in[0];
    const float* mask      = (const float*)d_in[1];
    const float* structure = (const float*)d_in[2];
    const float* triple    = (const float*)d_in[3];
    const float* Wq  = (const float*)d_in[4];
    const float* bq  = (const float*)d_in[5];
    const float* Wk  = (const float*)d_in[6];
    const float* bk  = (const float*)d_in[7];
    const float* Wv  = (const float*)d_in[8];
    const float* bv  = (const float*)d_in[9];
    const float* Wsq = (const float*)d_in[10];
    const float* bsq = (const float*)d_in[11];
    const float* Wsv = (const float*)d_in[12];
    const float* bsv = (const float*)d_in[13];
    const float* Wtq = (const float*)d_in[14];
    const float* btq = (const float*)d_in[15];
    const float* Wtk = (const float*)d_in[16];
    const float* btk = (const float*)d_in[17];
    float* out = (float*)d_out;

    cudaFuncSetAttribute(k_main, cudaFuncAttributeMaxDynamicSharedMemorySize, SMEM_MAIN);

    k_prep <<<256, 768>>>(Wq, Wk, Wv, Wsq, Wsv);
    k_qkv  <<<128, 256>>>(hs, bq, bk, bv);
    k_small<<<512, 256>>>(Wtq, btq, Wtk, btk);
    k_sqsv <<<1024, 256>>>(structure, bsq, bsv);
    k_sqw  <<<4096, 256>>>(Wtq, btq);
    k_main <<<1024, 512, SMEM_MAIN>>>(triple, mask);
    k_reduce<<<512, 256>>>(out);
}